// round 7
// baseline (speedup 1.0000x reference)
#include <cuda_runtime.h>
#include <math.h>
#include <stdint.h>

#define BATCH 32
#define NNETS 264
#define DIM   375
#define PAIRS 34716
#define PPAD  34720      // padded to multiple of 8
#define PSPL  20         // p-splits for big GEMM (20*217*8 = 34720)
#define STEPS 217
#define RRS   (11.0f/48.0f)

// -------- device scratch (no allocations allowed) --------
__device__ float g_A  [BATCH*NNETS*32];   // feats @ sm_w1[0:32]  (+ sm_b1 folded in)
__device__ float g_Bv [BATCH*NNETS*32];   // feats @ sm_w1[32:64]
__device__ float g_S  [BATCH*PPAD];       // similarity scores, zero-padded cols
__device__ float g_C1p[PSPL*BATCH*4096];  // partial c1
__device__ float g_C1 [BATCH*4096];       // rrelu(c1)
__device__ float g_c2p[8*BATCH*256];      // partial c2

// =====================================================================
// Kernel A: feature extractor + similarity layer-1 factorization
// 528 blocks x 128 threads, 16 rows (subject,net) per block
// =====================================================================
__global__ void __launch_bounds__(128) kA(
    const float* __restrict__ x,
    const float* __restrict__ w1, const float* __restrict__ b1,
    const float* __restrict__ w2, const float* __restrict__ b2,
    const float* __restrict__ w3, const float* __restrict__ b3,
    const float* __restrict__ sw1, const float* __restrict__ sb1)
{
    __shared__ float sx [16][376];
    __shared__ float sh1[16][68];
    __shared__ float sh2[16][68];
    __shared__ float sf [16][36];
    const int t = threadIdx.x;
    const int row0 = blockIdx.x * 16;

    for (int idx = t; idx < 16*DIM; idx += 128) {
        int r = idx / DIM;
        int d = idx - r*DIM;
        sx[r][d] = x[(size_t)(row0 + r)*DIM + d];
    }
    __syncthreads();

    const int r  = t >> 3;
    const int cg = t & 7;

    // ---- layer 1: 375 -> 64, rrelu ----
    {
        const int c0 = cg * 8;
        float acc[8];
        #pragma unroll
        for (int u = 0; u < 8; u++) acc[u] = 0.f;
        int d = 0;
        for (; d < 372; d += 4) {
            float4 xv = *reinterpret_cast<const float4*>(&sx[r][d]);
            float xa[4] = {xv.x, xv.y, xv.z, xv.w};
            #pragma unroll
            for (int dd = 0; dd < 4; dd++) {
                float xs1 = xa[dd];
                float4 wa = *reinterpret_cast<const float4*>(&w1[(size_t)(d+dd)*64 + c0]);
                float4 wb = *reinterpret_cast<const float4*>(&w1[(size_t)(d+dd)*64 + c0 + 4]);
                acc[0] += xs1*wa.x; acc[1] += xs1*wa.y; acc[2] += xs1*wa.z; acc[3] += xs1*wa.w;
                acc[4] += xs1*wb.x; acc[5] += xs1*wb.y; acc[6] += xs1*wb.z; acc[7] += xs1*wb.w;
            }
        }
        for (; d < DIM; d++) {
            float xs1 = sx[r][d];
            #pragma unroll
            for (int u = 0; u < 8; u++) acc[u] += xs1 * w1[(size_t)d*64 + c0 + u];
        }
        #pragma unroll
        for (int u = 0; u < 8; u++) {
            float v = acc[u] + b1[c0 + u];
            sh1[r][c0 + u] = (v >= 0.f) ? v : v * RRS;
        }
    }
    __syncthreads();

    // ---- layer 2: 64 -> 64, relu ----
    {
        const int c0 = cg * 8;
        float acc[8];
        #pragma unroll
        for (int u = 0; u < 8; u++) acc[u] = 0.f;
        for (int k = 0; k < 64; k += 4) {
            float4 hv = *reinterpret_cast<const float4*>(&sh1[r][k]);
            float ha[4] = {hv.x, hv.y, hv.z, hv.w};
            #pragma unroll
            for (int dd = 0; dd < 4; dd++) {
                float xs1 = ha[dd];
                float4 wa = *reinterpret_cast<const float4*>(&w2[(size_t)(k+dd)*64 + c0]);
                float4 wb = *reinterpret_cast<const float4*>(&w2[(size_t)(k+dd)*64 + c0 + 4]);
                acc[0] += xs1*wa.x; acc[1] += xs1*wa.y; acc[2] += xs1*wa.z; acc[3] += xs1*wa.w;
                acc[4] += xs1*wb.x; acc[5] += xs1*wb.y; acc[6] += xs1*wb.z; acc[7] += xs1*wb.w;
            }
        }
        #pragma unroll
        for (int u = 0; u < 8; u++)
            sh2[r][c0 + u] = fmaxf(acc[u] + b2[c0 + u], 0.f);
    }
    __syncthreads();

    // ---- layer 3: 64 -> 32 (no act) ----
    {
        const int c0 = cg * 4;
        float acc[4] = {0.f, 0.f, 0.f, 0.f};
        for (int k = 0; k < 64; k += 4) {
            float4 hv = *reinterpret_cast<const float4*>(&sh2[r][k]);
            float ha[4] = {hv.x, hv.y, hv.z, hv.w};
            #pragma unroll
            for (int dd = 0; dd < 4; dd++) {
                float xs1 = ha[dd];
                float4 wa = *reinterpret_cast<const float4*>(&w3[(size_t)(k+dd)*32 + c0]);
                acc[0] += xs1*wa.x; acc[1] += xs1*wa.y; acc[2] += xs1*wa.z; acc[3] += xs1*wa.w;
            }
        }
        #pragma unroll
        for (int u = 0; u < 4; u++) sf[r][c0 + u] = acc[u] + b3[c0 + u];
    }
    __syncthreads();

    // ---- similarity layer-1 factorization: a = feats@sw1_top (+b1), b = feats@sw1_bot ----
    {
        const int c0 = cg * 4;
        float aa[4] = {0.f,0.f,0.f,0.f};
        float bb[4] = {0.f,0.f,0.f,0.f};
        for (int k = 0; k < 32; k += 4) {
            float4 fv = *reinterpret_cast<const float4*>(&sf[r][k]);
            float fa[4] = {fv.x, fv.y, fv.z, fv.w};
            #pragma unroll
            for (int dd = 0; dd < 4; dd++) {
                float xs1 = fa[dd];
                float4 wa = *reinterpret_cast<const float4*>(&sw1[(size_t)(k+dd)*32 + c0]);
                float4 wb = *reinterpret_cast<const float4*>(&sw1[(size_t)(k+dd+32)*32 + c0]);
                aa[0] += xs1*wa.x; aa[1] += xs1*wa.y; aa[2] += xs1*wa.z; aa[3] += xs1*wa.w;
                bb[0] += xs1*wb.x; bb[1] += xs1*wb.y; bb[2] += xs1*wb.z; bb[3] += xs1*wb.w;
            }
        }
        size_t base = (size_t)(row0 + r)*32 + c0;
        #pragma unroll
        for (int u = 0; u < 4; u++) {
            g_A [base + u] = aa[u] + sb1[c0 + u];
            g_Bv[base + u] = bb[u];
        }
    }
}

// =====================================================================
// Kernel B: similarity MLP over all (b, i<j) pairs. Triangle tiling 32x32.
// grid (45, 32), 256 threads. Thread: fixed i, 4 j values.
// =====================================================================
__global__ void __launch_bounds__(256) kB(
    const float* __restrict__ smw2, const float* __restrict__ smb2,
    const float* __restrict__ smw3, const float* __restrict__ smb3,
    const float* __restrict__ smw4, const float* __restrict__ smb4)
{
    __shared__ float  bs[32][33];
    __shared__ float4 w2s[32][4];
    __shared__ float4 w3s[16][2];
    __shared__ float  w4s[8];
    __shared__ float  b2s[16];
    __shared__ float  b3s[8];
    __shared__ float  b4s;

    const int t = threadIdx.x;
    const int b = blockIdx.y;

    // zero the pad columns of g_S once
    if (blockIdx.x == 0 && blockIdx.y == 0 && t < 128) {
        int bb = t >> 2;
        g_S[(size_t)bb*PPAD + PAIRS + (t & 3)] = 0.f;
    }

    // decode triangle tile
    int ti = 0, rem = blockIdx.x;
    while (rem >= 9 - ti) { rem -= 9 - ti; ti++; }
    int tj = ti + rem;
    const int i0 = ti*32, j0 = tj*32;

    // stage weights
    for (int u = t; u < 512; u += 256) reinterpret_cast<float*>(w2s)[u] = smw2[u];
    for (int u = t; u < 128; u += 256) reinterpret_cast<float*>(w3s)[u] = smw3[u];
    if (t < 8)  w4s[t] = smw4[t];
    if (t < 16) b2s[t] = smb2[t];
    if (t >= 16 && t < 24) b3s[t-16] = smb3[t-16];
    if (t == 24) b4s = smb4[0];

    // stage b-vectors for the j tile
    for (int u = t; u < 32*32; u += 256) {
        int jl = u >> 5, c = u & 31;
        int j = j0 + jl;
        bs[jl][c] = (j < NNETS) ? g_Bv[((size_t)b*NNETS + j)*32 + c] : 0.f;
    }
    __syncthreads();

    const int il = t & 31;
    const int jg = t >> 5;
    const int i  = i0 + il;
    const bool ivalid = (i < NNETS);

    float a[32];
    if (ivalid) {
        #pragma unroll
        for (int u = 0; u < 8; u++) {
            float4 v = *reinterpret_cast<const float4*>(&g_A[((size_t)b*NNETS + i)*32 + u*4]);
            a[u*4+0]=v.x; a[u*4+1]=v.y; a[u*4+2]=v.z; a[u*4+3]=v.w;
        }
    }

    for (int q = 0; q < 4; q++) {
        int jl = jg + 8*q;
        int j  = j0 + jl;
        if (!ivalid || j >= NNETS || i >= j) continue;

        float h2[16];
        #pragma unroll
        for (int o = 0; o < 16; o++) h2[o] = b2s[o];
        #pragma unroll
        for (int k = 0; k < 32; k++) {
            float v = fmaxf(a[k] + bs[jl][k], 0.f);   // relu(pair@sm_w1 + sm_b1)
            #pragma unroll
            for (int q4 = 0; q4 < 4; q4++) {
                float4 wv = w2s[k][q4];
                h2[q4*4+0] += v*wv.x; h2[q4*4+1] += v*wv.y;
                h2[q4*4+2] += v*wv.z; h2[q4*4+3] += v*wv.w;
            }
        }
        float h3[8];
        #pragma unroll
        for (int o = 0; o < 8; o++) h3[o] = b3s[o];
        #pragma unroll
        for (int k = 0; k < 16; k++) {
            float v = fmaxf(h2[k], 0.f);
            #pragma unroll
            for (int q4 = 0; q4 < 2; q4++) {
                float4 wv = w3s[k][q4];
                h3[q4*4+0] += v*wv.x; h3[q4*4+1] += v*wv.y;
                h3[q4*4+2] += v*wv.z; h3[q4*4+3] += v*wv.w;
            }
        }
        float sv = b4s;
        #pragma unroll
        for (int k = 0; k < 8; k++) sv += fmaxf(h3[k], 0.f) * w4s[k];
        float s = tanhf(sv);

        int p = ((i * (2*NNETS - i - 1)) >> 1) + (j - i - 1);
        g_S[(size_t)b*PPAD + p] = s;
    }
}

// =====================================================================
// Kernel C: c1 partials = S[32,PPAD] @ cl_w1[PAIRS,4096] via tf32 mma
// grid 640 = 32 k-blocks (128 cols) x 20 p-splits; 256 threads (8 warps)
// =====================================================================
__device__ __forceinline__ void mma_tf32(float c[4], const float a[4], const float bb[2])
{
    uint32_t a0 = __float_as_uint(a[0]), a1 = __float_as_uint(a[1]);
    uint32_t a2 = __float_as_uint(a[2]), a3 = __float_as_uint(a[3]);
    uint32_t b0 = __float_as_uint(bb[0]), b1 = __float_as_uint(bb[1]);
    asm volatile(
        "mma.sync.aligned.m16n8k8.row.col.f32.tf32.tf32.f32 "
        "{%0,%1,%2,%3}, {%4,%5,%6,%7}, {%8,%9}, {%0,%1,%2,%3};\n"
        : "+f"(c[0]), "+f"(c[1]), "+f"(c[2]), "+f"(c[3])
        : "r"(a0), "r"(a1), "r"(a2), "r"(a3), "r"(b0), "r"(b1));
}

__global__ void __launch_bounds__(256) kC(const float* __restrict__ W)
{
    const int kb   = blockIdx.x & 31;
    const int ps   = blockIdx.x >> 5;
    const int warp = threadIdx.x >> 5;
    const int lane = threadIdx.x & 31;
    const int gid  = lane >> 2;
    const int tg   = lane & 3;
    const int kbase = kb*128 + warp*16;

    float c[2][2][4];
    #pragma unroll
    for (int m = 0; m < 2; m++)
        #pragma unroll
        for (int n = 0; n < 2; n++)
            #pragma unroll
            for (int u = 0; u < 4; u++) c[m][n][u] = 0.f;

    int p0 = ps * STEPS * 8;
    #pragma unroll 2
    for (int st = 0; st < STEPS; st++, p0 += 8) {
        float a0[4], a1[4];
        const float* Sp = g_S + (size_t)gid*PPAD + p0 + tg;
        a0[0] = Sp[0];            a0[1] = Sp[8*PPAD];
        a0[2] = Sp[4];            a0[3] = Sp[8*PPAD + 4];
        a1[0] = Sp[16*PPAD];      a1[1] = Sp[24*PPAD];
        a1[2] = Sp[16*PPAD + 4];  a1[3] = Sp[24*PPAD + 4];

        int pr0 = p0 + tg;     if (pr0 > PAIRS-1) pr0 = PAIRS-1;
        int pr1 = p0 + tg + 4; if (pr1 > PAIRS-1) pr1 = PAIRS-1;
        const float* W0 = W + (size_t)pr0*4096 + kbase + gid;
        const float* W1 = W + (size_t)pr1*4096 + kbase + gid;
        float b0[2], b1[2];
        b0[0] = W0[0]; b0[1] = W1[0];
        b1[0] = W0[8]; b1[1] = W1[8];

        mma_tf32(c[0][0], a0, b0);
        mma_tf32(c[0][1], a0, b1);
        mma_tf32(c[1][0], a1, b0);
        mma_tf32(c[1][1], a1, b1);
    }

    #pragma unroll
    for (int mt = 0; mt < 2; mt++)
        #pragma unroll
        for (int nt = 0; nt < 2; nt++) {
            int col = kbase + nt*8 + tg*2;
            int row = mt*16 + gid;
            float* out = g_C1p + ((size_t)ps*32 + row)*4096 + col;
            *reinterpret_cast<float2*>(out)          = make_float2(c[mt][nt][0], c[mt][nt][1]);
            *reinterpret_cast<float2*>(out + 8*4096) = make_float2(c[mt][nt][2], c[mt][nt][3]);
        }
}

// =====================================================================
// Kernel D: reduce c1 partials + bias + rrelu -> g_C1
// =====================================================================
__global__ void __launch_bounds__(256) kD(const float* __restrict__ clb1)
{
    int idx = blockIdx.x*256 + threadIdx.x;   // < 131072
    float acc = 0.f;
    #pragma unroll
    for (int ps = 0; ps < PSPL; ps++) acc += g_C1p[(size_t)ps*131072 + idx];
    float v = acc + clb1[idx & 4095];
    g_C1[idx] = (v >= 0.f) ? v : v * RRS;
}

// =====================================================================
// Kernel E: c2 partials = g_C1[32,4096] @ cl_w2[4096,256]
// grid 128 = 16 kgroups x 8 p-splits; 256 threads
// =====================================================================
__global__ void __launch_bounds__(256) kE(const float* __restrict__ w2)
{
    const int kg = blockIdx.x & 15;
    const int ps = blockIdx.x >> 4;
    const int t  = threadIdx.x;
    const int kcol = kg*16 + (t & 15);
    const int tb = t >> 4;
    const int b0 = tb*2, b1 = b0 + 1;
    float acc0 = 0.f, acc1 = 0.f;
    const float* c1a = g_C1 + (size_t)b0*4096;
    const float* c1b = g_C1 + (size_t)b1*4096;
    const int pstart = ps*512;
    for (int p = pstart; p < pstart + 512; p++) {
        float w = w2[(size_t)p*256 + kcol];
        acc0 += c1a[p]*w;
        acc1 += c1b[p]*w;
    }
    g_c2p[((size_t)ps*32 + b0)*256 + kcol] = acc0;
    g_c2p[((size_t)ps*32 + b1)*256 + kcol] = acc1;
}

// =====================================================================
// Kernel F: reduce c2 + relu, c3, c4, log_softmax. Single block.
// =====================================================================
__global__ void __launch_bounds__(256) kF(
    const float* __restrict__ clb2,
    const float* __restrict__ w3, const float* __restrict__ clb3,
    const float* __restrict__ w4, const float* __restrict__ clb4,
    float* __restrict__ out)
{
    __shared__ float c2s[32][256];
    __shared__ float c3s[32][65];
    const int t = threadIdx.x;

    for (int idx = t; idx < 8192; idx += 256) {
        float acc = 0.f;
        #pragma unroll
        for (int ps = 0; ps < 8; ps++) acc += g_c2p[(size_t)ps*8192 + idx];
        acc += clb2[idx & 255];
        c2s[idx >> 8][idx & 255] = fmaxf(acc, 0.f);
    }
    __syncthreads();

    for (int o = t; o < 2048; o += 256) {
        int b = o >> 6, k = o & 63;
        float acc = clb3[k];
        for (int p = 0; p < 256; p++) acc += c2s[b][p] * w3[(size_t)p*64 + k];
        c3s[b][k] = fmaxf(acc, 0.f);
    }
    __syncthreads();

    if (t < 32) {
        const int b = t;
        float l[3];
        #pragma unroll
        for (int j = 0; j < 3; j++) {
            float acc = clb4[j];
            for (int k = 0; k < 64; k++) acc += c3s[b][k] * w4[k*3 + j];
            l[j] = acc;
        }
        float m = fmaxf(l[0], fmaxf(l[1], l[2]));
        float se = expf(l[0]-m) + expf(l[1]-m) + expf(l[2]-m);
        float ls = m + logf(se);
        out[b*3+0] = l[0] - ls;
        out[b*3+1] = l[1] - ls;
        out[b*3+2] = l[2] - ls;
    }
}

// =====================================================================
extern "C" void kernel_launch(void* const* d_in, const int* in_sizes, int n_in,
                              void* d_out, int out_size)
{
    const float* x    = (const float*)d_in[0];
    const float* few1 = (const float*)d_in[1];
    const float* feb1 = (const float*)d_in[2];
    const float* few2 = (const float*)d_in[3];
    const float* feb2 = (const float*)d_in[4];
    const float* few3 = (const float*)d_in[5];
    const float* feb3 = (const float*)d_in[6];
    const float* smw1 = (const float*)d_in[7];
    const float* smb1 = (const float*)d_in[8];
    const float* smw2 = (const float*)d_in[9];
    const float* smb2 = (const float*)d_in[10];
    const float* smw3 = (const float*)d_in[11];
    const float* smb3 = (const float*)d_in[12];
    const float* smw4 = (const float*)d_in[13];
    const float* smb4 = (const float*)d_in[14];
    const float* clw1 = (const float*)d_in[15];
    const float* clb1 = (const float*)d_in[16];
    const float* clw2 = (const float*)d_in[17];
    const float* clb2 = (const float*)d_in[18];
    const float* clw3 = (const float*)d_in[19];
    const float* clb3 = (const float*)d_in[20];
    const float* clw4 = (const float*)d_in[21];
    const float* clb4 = (const float*)d_in[22];

    kA<<<528, 128>>>(x, few1, feb1, few2, feb2, few3, feb3, smw1, smb1);
    kB<<<dim3(45, 32), 256>>>(smw2, smb2, smw3, smb3, smw4, smb4);
    kC<<<640, 256>>>(clw1);
    kD<<<512, 256>>>(clb1);
    kE<<<128, 256>>>(clw2);
    kF<<<1, 256>>>(clb2, clw3, clb3, clw4, clb4, (float*)d_out);
}

// round 8
// speedup vs baseline: 1.0062x; 1.0062x over previous
#include <cuda_runtime.h>
#include <math.h>
#include <stdint.h>

#define BATCH 32
#define NNETS 264
#define DIM   375
#define PAIRS 34716
#define PPAD  34720      // padded to multiple of 8
#define PSPL  20         // p-splits for big GEMM (20*217*8 = 34720)
#define STEPS 217
#define RRS   (11.0f/48.0f)

// -------- device scratch (no allocations allowed) --------
__device__ float g_A  [BATCH*NNETS*32];   // feats @ sm_w1[0:32]  (+ sm_b1 folded in)
__device__ float g_Bv [BATCH*NNETS*32];   // feats @ sm_w1[32:64]
__device__ float g_S  [BATCH*PPAD];       // similarity scores, zero-padded cols
__device__ float g_C1p[PSPL*BATCH*4096];  // partial c1
__device__ float g_C1 [BATCH*4096];       // rrelu(c1)
__device__ float g_c2p[8*BATCH*256];      // partial c2

// =====================================================================
// Kernel A: feature extractor + similarity layer-1 factorization
// 528 blocks x 128 threads, 16 rows (subject,net) per block
// =====================================================================
__global__ void __launch_bounds__(128) kA(
    const float* __restrict__ x,
    const float* __restrict__ w1, const float* __restrict__ b1,
    const float* __restrict__ w2, const float* __restrict__ b2,
    const float* __restrict__ w3, const float* __restrict__ b3,
    const float* __restrict__ sw1, const float* __restrict__ sb1)
{
    __shared__ float sx [16][376];
    __shared__ float sh1[16][68];
    __shared__ float sh2[16][68];
    __shared__ float sf [16][36];
    const int t = threadIdx.x;
    const int row0 = blockIdx.x * 16;

    for (int idx = t; idx < 16*DIM; idx += 128) {
        int r = idx / DIM;
        int d = idx - r*DIM;
        sx[r][d] = x[(size_t)(row0 + r)*DIM + d];
    }
    __syncthreads();

    const int r  = t >> 3;
    const int cg = t & 7;

    // ---- layer 1: 375 -> 64, rrelu ----
    {
        const int c0 = cg * 8;
        float acc[8];
        #pragma unroll
        for (int u = 0; u < 8; u++) acc[u] = 0.f;
        int d = 0;
        for (; d < 372; d += 4) {
            float4 xv = *reinterpret_cast<const float4*>(&sx[r][d]);
            float xa[4] = {xv.x, xv.y, xv.z, xv.w};
            #pragma unroll
            for (int dd = 0; dd < 4; dd++) {
                float xs1 = xa[dd];
                float4 wa = *reinterpret_cast<const float4*>(&w1[(size_t)(d+dd)*64 + c0]);
                float4 wb = *reinterpret_cast<const float4*>(&w1[(size_t)(d+dd)*64 + c0 + 4]);
                acc[0] += xs1*wa.x; acc[1] += xs1*wa.y; acc[2] += xs1*wa.z; acc[3] += xs1*wa.w;
                acc[4] += xs1*wb.x; acc[5] += xs1*wb.y; acc[6] += xs1*wb.z; acc[7] += xs1*wb.w;
            }
        }
        for (; d < DIM; d++) {
            float xs1 = sx[r][d];
            #pragma unroll
            for (int u = 0; u < 8; u++) acc[u] += xs1 * w1[(size_t)d*64 + c0 + u];
        }
        #pragma unroll
        for (int u = 0; u < 8; u++) {
            float v = acc[u] + b1[c0 + u];
            sh1[r][c0 + u] = (v >= 0.f) ? v : v * RRS;
        }
    }
    __syncthreads();

    // ---- layer 2: 64 -> 64, relu ----
    {
        const int c0 = cg * 8;
        float acc[8];
        #pragma unroll
        for (int u = 0; u < 8; u++) acc[u] = 0.f;
        for (int k = 0; k < 64; k += 4) {
            float4 hv = *reinterpret_cast<const float4*>(&sh1[r][k]);
            float ha[4] = {hv.x, hv.y, hv.z, hv.w};
            #pragma unroll
            for (int dd = 0; dd < 4; dd++) {
                float xs1 = ha[dd];
                float4 wa = *reinterpret_cast<const float4*>(&w2[(size_t)(k+dd)*64 + c0]);
                float4 wb = *reinterpret_cast<const float4*>(&w2[(size_t)(k+dd)*64 + c0 + 4]);
                acc[0] += xs1*wa.x; acc[1] += xs1*wa.y; acc[2] += xs1*wa.z; acc[3] += xs1*wa.w;
                acc[4] += xs1*wb.x; acc[5] += xs1*wb.y; acc[6] += xs1*wb.z; acc[7] += xs1*wb.w;
            }
        }
        #pragma unroll
        for (int u = 0; u < 8; u++)
            sh2[r][c0 + u] = fmaxf(acc[u] + b2[c0 + u], 0.f);
    }
    __syncthreads();

    // ---- layer 3: 64 -> 32 (no act) ----
    {
        const int c0 = cg * 4;
        float acc[4] = {0.f, 0.f, 0.f, 0.f};
        for (int k = 0; k < 64; k += 4) {
            float4 hv = *reinterpret_cast<const float4*>(&sh2[r][k]);
            float ha[4] = {hv.x, hv.y, hv.z, hv.w};
            #pragma unroll
            for (int dd = 0; dd < 4; dd++) {
                float xs1 = ha[dd];
                float4 wa = *reinterpret_cast<const float4*>(&w3[(size_t)(k+dd)*32 + c0]);
                acc[0] += xs1*wa.x; acc[1] += xs1*wa.y; acc[2] += xs1*wa.z; acc[3] += xs1*wa.w;
            }
        }
        #pragma unroll
        for (int u = 0; u < 4; u++) sf[r][c0 + u] = acc[u] + b3[c0 + u];
    }
    __syncthreads();

    // ---- similarity layer-1 factorization: a = feats@sw1_top (+b1), b = feats@sw1_bot ----
    {
        const int c0 = cg * 4;
        float aa[4] = {0.f,0.f,0.f,0.f};
        float bb[4] = {0.f,0.f,0.f,0.f};
        for (int k = 0; k < 32; k += 4) {
            float4 fv = *reinterpret_cast<const float4*>(&sf[r][k]);
            float fa[4] = {fv.x, fv.y, fv.z, fv.w};
            #pragma unroll
            for (int dd = 0; dd < 4; dd++) {
                float xs1 = fa[dd];
                float4 wa = *reinterpret_cast<const float4*>(&sw1[(size_t)(k+dd)*32 + c0]);
                float4 wb = *reinterpret_cast<const float4*>(&sw1[(size_t)(k+dd+32)*32 + c0]);
                aa[0] += xs1*wa.x; aa[1] += xs1*wa.y; aa[2] += xs1*wa.z; aa[3] += xs1*wa.w;
                bb[0] += xs1*wb.x; bb[1] += xs1*wb.y; bb[2] += xs1*wb.z; bb[3] += xs1*wb.w;
            }
        }
        size_t base = (size_t)(row0 + r)*32 + c0;
        #pragma unroll
        for (int u = 0; u < 4; u++) {
            g_A [base + u] = aa[u] + sb1[c0 + u];
            g_Bv[base + u] = bb[u];
        }
    }
}

// =====================================================================
// Kernel B: similarity MLP over all (b, i<j) pairs. Triangle tiling 32x32.
// grid (45, 32), 256 threads. Thread: fixed i, 4 j values.
// =====================================================================
__global__ void __launch_bounds__(256) kB(
    const float* __restrict__ smw2, const float* __restrict__ smb2,
    const float* __restrict__ smw3, const float* __restrict__ smb3,
    const float* __restrict__ smw4, const float* __restrict__ smb4)
{
    __shared__ float  bs[32][33];
    __shared__ float4 w2s[32][4];
    __shared__ float4 w3s[16][2];
    __shared__ float  w4s[8];
    __shared__ float  b2s[16];
    __shared__ float  b3s[8];
    __shared__ float  b4s;

    const int t = threadIdx.x;
    const int b = blockIdx.y;

    // zero the pad columns of g_S once
    if (blockIdx.x == 0 && blockIdx.y == 0 && t < 128) {
        int bb = t >> 2;
        g_S[(size_t)bb*PPAD + PAIRS + (t & 3)] = 0.f;
    }

    // decode triangle tile
    int ti = 0, rem = blockIdx.x;
    while (rem >= 9 - ti) { rem -= 9 - ti; ti++; }
    int tj = ti + rem;
    const int i0 = ti*32, j0 = tj*32;

    // stage weights
    for (int u = t; u < 512; u += 256) reinterpret_cast<float*>(w2s)[u] = smw2[u];
    for (int u = t; u < 128; u += 256) reinterpret_cast<float*>(w3s)[u] = smw3[u];
    if (t < 8)  w4s[t] = smw4[t];
    if (t < 16) b2s[t] = smb2[t];
    if (t >= 16 && t < 24) b3s[t-16] = smb3[t-16];
    if (t == 24) b4s = smb4[0];

    // stage b-vectors for the j tile
    for (int u = t; u < 32*32; u += 256) {
        int jl = u >> 5, c = u & 31;
        int j = j0 + jl;
        bs[jl][c] = (j < NNETS) ? g_Bv[((size_t)b*NNETS + j)*32 + c] : 0.f;
    }
    __syncthreads();

    const int il = t & 31;
    const int jg = t >> 5;
    const int i  = i0 + il;
    const bool ivalid = (i < NNETS);

    float a[32];
    if (ivalid) {
        #pragma unroll
        for (int u = 0; u < 8; u++) {
            float4 v = *reinterpret_cast<const float4*>(&g_A[((size_t)b*NNETS + i)*32 + u*4]);
            a[u*4+0]=v.x; a[u*4+1]=v.y; a[u*4+2]=v.z; a[u*4+3]=v.w;
        }
    }

    for (int q = 0; q < 4; q++) {
        int jl = jg + 8*q;
        int j  = j0 + jl;
        if (!ivalid || j >= NNETS || i >= j) continue;

        float h2[16];
        #pragma unroll
        for (int o = 0; o < 16; o++) h2[o] = b2s[o];
        #pragma unroll
        for (int k = 0; k < 32; k++) {
            float v = fmaxf(a[k] + bs[jl][k], 0.f);   // relu(pair@sm_w1 + sm_b1)
            #pragma unroll
            for (int q4 = 0; q4 < 4; q4++) {
                float4 wv = w2s[k][q4];
                h2[q4*4+0] += v*wv.x; h2[q4*4+1] += v*wv.y;
                h2[q4*4+2] += v*wv.z; h2[q4*4+3] += v*wv.w;
            }
        }
        float h3[8];
        #pragma unroll
        for (int o = 0; o < 8; o++) h3[o] = b3s[o];
        #pragma unroll
        for (int k = 0; k < 16; k++) {
            float v = fmaxf(h2[k], 0.f);
            #pragma unroll
            for (int q4 = 0; q4 < 2; q4++) {
                float4 wv = w3s[k][q4];
                h3[q4*4+0] += v*wv.x; h3[q4*4+1] += v*wv.y;
                h3[q4*4+2] += v*wv.z; h3[q4*4+3] += v*wv.w;
            }
        }
        float sv = b4s;
        #pragma unroll
        for (int k = 0; k < 8; k++) sv += fmaxf(h3[k], 0.f) * w4s[k];
        float s = tanhf(sv);

        int p = ((i * (2*NNETS - i - 1)) >> 1) + (j - i - 1);
        g_S[(size_t)b*PPAD + p] = s;
    }
}

// =====================================================================
// Kernel C: c1 partials = S[32,PPAD] @ cl_w1[PAIRS,4096] via tf32 mma
// grid 640 = 32 k-blocks (128 cols) x 20 p-splits; 256 threads (8 warps)
// =====================================================================
__device__ __forceinline__ void mma_tf32(float c[4], const float a[4], const float bb[2])
{
    uint32_t a0 = __float_as_uint(a[0]), a1 = __float_as_uint(a[1]);
    uint32_t a2 = __float_as_uint(a[2]), a3 = __float_as_uint(a[3]);
    uint32_t b0 = __float_as_uint(bb[0]), b1 = __float_as_uint(bb[1]);
    asm volatile(
        "mma.sync.aligned.m16n8k8.row.col.f32.tf32.tf32.f32 "
        "{%0,%1,%2,%3}, {%4,%5,%6,%7}, {%8,%9}, {%0,%1,%2,%3};\n"
        : "+f"(c[0]), "+f"(c[1]), "+f"(c[2]), "+f"(c[3])
        : "r"(a0), "r"(a1), "r"(a2), "r"(a3), "r"(b0), "r"(b1));
}

__global__ void __launch_bounds__(256) kC(const float* __restrict__ W)
{
    const int kb   = blockIdx.x & 31;
    const int ps   = blockIdx.x >> 5;
    const int warp = threadIdx.x >> 5;
    const int lane = threadIdx.x & 31;
    const int gid  = lane >> 2;
    const int tg   = lane & 3;
    const int kbase = kb*128 + warp*16;

    float c[2][2][4];
    #pragma unroll
    for (int m = 0; m < 2; m++)
        #pragma unroll
        for (int n = 0; n < 2; n++)
            #pragma unroll
            for (int u = 0; u < 4; u++) c[m][n][u] = 0.f;

    int p0 = ps * STEPS * 8;
    #pragma unroll 2
    for (int st = 0; st < STEPS; st++, p0 += 8) {
        float a0[4], a1[4];
        const float* Sp = g_S + (size_t)gid*PPAD + p0 + tg;
        a0[0] = Sp[0];            a0[1] = Sp[8*PPAD];
        a0[2] = Sp[4];            a0[3] = Sp[8*PPAD + 4];
        a1[0] = Sp[16*PPAD];      a1[1] = Sp[24*PPAD];
        a1[2] = Sp[16*PPAD + 4];  a1[3] = Sp[24*PPAD + 4];

        int pr0 = p0 + tg;     if (pr0 > PAIRS-1) pr0 = PAIRS-1;
        int pr1 = p0 + tg + 4; if (pr1 > PAIRS-1) pr1 = PAIRS-1;
        const float* W0 = W + (size_t)pr0*4096 + kbase + gid;
        const float* W1 = W + (size_t)pr1*4096 + kbase + gid;
        float b0[2], b1[2];
        b0[0] = W0[0]; b0[1] = W1[0];
        b1[0] = W0[8]; b1[1] = W1[8];

        mma_tf32(c[0][0], a0, b0);
        mma_tf32(c[0][1], a0, b1);
        mma_tf32(c[1][0], a1, b0);
        mma_tf32(c[1][1], a1, b1);
    }

    #pragma unroll
    for (int mt = 0; mt < 2; mt++)
        #pragma unroll
        for (int nt = 0; nt < 2; nt++) {
            int col = kbase + nt*8 + tg*2;
            int row = mt*16 + gid;
            float* out = g_C1p + ((size_t)ps*32 + row)*4096 + col;
            *reinterpret_cast<float2*>(out)          = make_float2(c[mt][nt][0], c[mt][nt][1]);
            *reinterpret_cast<float2*>(out + 8*4096) = make_float2(c[mt][nt][2], c[mt][nt][3]);
        }
}

// =====================================================================
// Kernel D: reduce c1 partials + bias + rrelu -> g_C1
// =====================================================================
__global__ void __launch_bounds__(256) kD(const float* __restrict__ clb1)
{
    int idx = blockIdx.x*256 + threadIdx.x;   // < 131072
    float acc = 0.f;
    #pragma unroll
    for (int ps = 0; ps < PSPL; ps++) acc += g_C1p[(size_t)ps*131072 + idx];
    float v = acc + clb1[idx & 4095];
    g_C1[idx] = (v >= 0.f) ? v : v * RRS;
}

// =====================================================================
// Kernel E: c2 partials = g_C1[32,4096] @ cl_w2[4096,256]
// grid 128 = 16 kgroups x 8 p-splits; 256 threads
// =====================================================================
__global__ void __launch_bounds__(256) kE(const float* __restrict__ w2)
{
    const int kg = blockIdx.x & 15;
    const int ps = blockIdx.x >> 4;
    const int t  = threadIdx.x;
    const int kcol = kg*16 + (t & 15);
    const int tb = t >> 4;
    const int b0 = tb*2, b1 = b0 + 1;
    float acc0 = 0.f, acc1 = 0.f;
    const float* c1a = g_C1 + (size_t)b0*4096;
    const float* c1b = g_C1 + (size_t)b1*4096;
    const int pstart = ps*512;
    for (int p = pstart; p < pstart + 512; p++) {
        float w = w2[(size_t)p*256 + kcol];
        acc0 += c1a[p]*w;
        acc1 += c1b[p]*w;
    }
    g_c2p[((size_t)ps*32 + b0)*256 + kcol] = acc0;
    g_c2p[((size_t)ps*32 + b1)*256 + kcol] = acc1;
}

// =====================================================================
// Kernel F: reduce c2 + relu, c3, c4, log_softmax. Single block.
// =====================================================================
__global__ void __launch_bounds__(256) kF(
    const float* __restrict__ clb2,
    const float* __restrict__ w3, const float* __restrict__ clb3,
    const float* __restrict__ w4, const float* __restrict__ clb4,
    float* __restrict__ out)
{
    __shared__ float c2s[32][256];
    __shared__ float c3s[32][65];
    const int t = threadIdx.x;

    for (int idx = t; idx < 8192; idx += 256) {
        float acc = 0.f;
        #pragma unroll
        for (int ps = 0; ps < 8; ps++) acc += g_c2p[(size_t)ps*8192 + idx];
        acc += clb2[idx & 255];
        c2s[idx >> 8][idx & 255] = fmaxf(acc, 0.f);
    }
    __syncthreads();

    for (int o = t; o < 2048; o += 256) {
        int b = o >> 6, k = o & 63;
        float acc = clb3[k];
        for (int p = 0; p < 256; p++) acc += c2s[b][p] * w3[(size_t)p*64 + k];
        c3s[b][k] = fmaxf(acc, 0.f);
    }
    __syncthreads();

    if (t < 32) {
        const int b = t;
        float l[3];
        #pragma unroll
        for (int j = 0; j < 3; j++) {
            float acc = clb4[j];
            for (int k = 0; k < 64; k++) acc += c3s[b][k] * w4[k*3 + j];
            l[j] = acc;
        }
        float m = fmaxf(l[0], fmaxf(l[1], l[2]));
        float se = expf(l[0]-m) + expf(l[1]-m) + expf(l[2]-m);
        float ls = m + logf(se);
        out[b*3+0] = l[0] - ls;
        out[b*3+1] = l[1] - ls;
        out[b*3+2] = l[2] - ls;
    }
}

// =====================================================================
extern "C" void kernel_launch(void* const* d_in, const int* in_sizes, int n_in,
                              void* d_out, int out_size)
{
    const float* x    = (const float*)d_in[0];
    const float* few1 = (const float*)d_in[1];
    const float* feb1 = (const float*)d_in[2];
    const float* few2 = (const float*)d_in[3];
    const float* feb2 = (const float*)d_in[4];
    const float* few3 = (const float*)d_in[5];
    const float* feb3 = (const float*)d_in[6];
    const float* smw1 = (const float*)d_in[7];
    const float* smb1 = (const float*)d_in[8];
    const float* smw2 = (const float*)d_in[9];
    const float* smb2 = (const float*)d_in[10];
    const float* smw3 = (const float*)d_in[11];
    const float* smb3 = (const float*)d_in[12];
    const float* smw4 = (const float*)d_in[13];
    const float* smb4 = (const float*)d_in[14];
    const float* clw1 = (const float*)d_in[15];
    const float* clb1 = (const float*)d_in[16];
    const float* clw2 = (const float*)d_in[17];
    const float* clb2 = (const float*)d_in[18];
    const float* clw3 = (const float*)d_in[19];
    const float* clb3 = (const float*)d_in[20];
    const float* clw4 = (const float*)d_in[21];
    const float* clb4 = (const float*)d_in[22];

    kA<<<528, 128>>>(x, few1, feb1, few2, feb2, few3, feb3, smw1, smb1);
    kB<<<dim3(45, 32), 256>>>(smw2, smb2, smw3, smb3, smw4, smb4);
    kC<<<640, 256>>>(clw1);
    kD<<<512, 256>>>(clb1);
    kE<<<128, 256>>>(clw2);
    kF<<<1, 256>>>(clb2, clw3, clb3, clw4, clb4, (float*)d_out);
}